// round 1
// baseline (speedup 1.0000x reference)
#include <cuda_runtime.h>
#include <cuda_bf16.h>
#include <math.h>

#define BATCH 256
#define SEQ   256
#define EMB   1024
#define HID   1024
#define NCLS  32000
#define G4    4096          // 4 gates * HID
#define WROW  2048          // EMB + HID
#define HB    (BATCH*HID)   // 262144
#define HB2   (2*BATCH*HID) // 524288 (2 dirs)

// Scratch (device globals: allocation-free rule)
static __device__ __nv_bfloat16 g_XW[(size_t)2 * SEQ * BATCH * G4]; // 1 GiB, layout [d][t][b][col*4+gate]
static __device__ float g_h[2 * HB2];   // [pingpong buf][dir][b][col]
static __device__ float g_c[HB2];       // [dir][b][col]
static __device__ float g_hsum[HB];     // h1 + h2

__global__ void init_kernel()
{
    int idx = blockIdx.x * blockDim.x + threadIdx.x;
    if (idx < 2 * HB2) g_h[idx] = 0.f;
    if (idx < HB2)     g_c[idx] = 0.f;
}

// ---------------------------------------------------------------------------
// Shared 128x128x8 fp32 GEMM core, double-buffered smem, 8x8 per thread.
// ---------------------------------------------------------------------------
__device__ __forceinline__ void gemm_core(
    const float* __restrict__ aptr, const float* __restrict__ bptr,
    float (&acc)[8][8],
    float (*As)[8][128], float (*Bs)[8][128],
    int a_m, int a_k, int b_n, int b_k, int r0, int c0, int nit)
{
    float4 pa = *(const float4*)(aptr + a_k);
    float4 pb = *(const float4*)(bptr + b_k);
    As[0][a_k+0][a_m]=pa.x; As[0][a_k+1][a_m]=pa.y; As[0][a_k+2][a_m]=pa.z; As[0][a_k+3][a_m]=pa.w;
    Bs[0][b_k+0][b_n]=pb.x; Bs[0][b_k+1][b_n]=pb.y; Bs[0][b_k+2][b_n]=pb.z; Bs[0][b_k+3][b_n]=pb.w;
    __syncthreads();

    for (int it = 0; it < nit; ++it) {
        int cur = it & 1;
        if (it + 1 < nit) {
            int k0 = (it + 1) * 8;
            pa = *(const float4*)(aptr + k0 + a_k);
            pb = *(const float4*)(bptr + k0 + b_k);
        }
#pragma unroll
        for (int kk = 0; kk < 8; ++kk) {
            float4 x0 = *(const float4*)&As[cur][kk][r0];
            float4 x1 = *(const float4*)&As[cur][kk][r0+4];
            float4 y0 = *(const float4*)&Bs[cur][kk][c0];
            float4 y1 = *(const float4*)&Bs[cur][kk][c0+4];
            float a[8] = {x0.x,x0.y,x0.z,x0.w,x1.x,x1.y,x1.z,x1.w};
            float b[8] = {y0.x,y0.y,y0.z,y0.w,y1.x,y1.y,y1.z,y1.w};
#pragma unroll
            for (int i = 0; i < 8; ++i)
#pragma unroll
                for (int j = 0; j < 8; ++j)
                    acc[i][j] = fmaf(a[i], b[j], acc[i][j]);
        }
        if (it + 1 < nit) {
            int nxt = cur ^ 1;
            As[nxt][a_k+0][a_m]=pa.x; As[nxt][a_k+1][a_m]=pa.y; As[nxt][a_k+2][a_m]=pa.z; As[nxt][a_k+3][a_m]=pa.w;
            Bs[nxt][b_k+0][b_n]=pb.x; Bs[nxt][b_k+1][b_n]=pb.y; Bs[nxt][b_k+2][b_n]=pb.z; Bs[nxt][b_k+3][b_n]=pb.w;
            __syncthreads();
        }
    }
}

// ---------------------------------------------------------------------------
// Kernel 1: XW[d][t][b][col*4+gi] = C[X[b][t]] . Wx[d,gi][col]
// GEMM: M = T*B (m = t*256 + b), N = 8192 (gate-major: n>>10 selects weight),
// K = 1024 (x-part of W rows).
// ---------------------------------------------------------------------------
__global__ __launch_bounds__(256) void xproj_kernel(
    const int* __restrict__ X, const float* __restrict__ C,
    const float* __restrict__ W0, const float* __restrict__ W1,
    const float* __restrict__ W2, const float* __restrict__ W3,
    const float* __restrict__ W4, const float* __restrict__ W5,
    const float* __restrict__ W6, const float* __restrict__ W7)
{
    __shared__ __align__(16) float As[2][8][128];
    __shared__ __align__(16) float Bs[2][8][128];
    __shared__ int toks[128];

    const float* Ws[8] = {W0,W1,W2,W3,W4,W5,W6,W7};

    const int tid   = threadIdx.x;
    const int nbase = blockIdx.x * 128;   // over 8192
    const int mbase = blockIdx.y * 128;   // over 65536

    if (tid < 128) {
        int m = mbase + tid;
        toks[tid] = X[(m & 255) * SEQ + (m >> 8)];   // X[b][t], m = t*256+b
    }

    const int a_m = tid >> 1, a_k = (tid & 1) * 4;
    const int b_n = tid >> 1, b_k = (tid & 1) * 4;
    const int ng = nbase + b_n;
    const float* bptr = Ws[ng >> 10] + (size_t)(ng & 1023) * WROW;  // x part (offset 0)
    __syncthreads();
    const float* aptr = C + (size_t)toks[a_m] * EMB;

    float acc[8][8];
#pragma unroll
    for (int i = 0; i < 8; ++i)
#pragma unroll
        for (int j = 0; j < 8; ++j) acc[i][j] = 0.f;

    const int r0 = (tid >> 4) * 8;
    const int c0 = (tid & 15) * 8;

    gemm_core(aptr, bptr, acc, As, Bs, a_m, a_k, b_n, b_k, r0, c0, EMB / 8);

#pragma unroll
    for (int i = 0; i < 8; ++i) {
        int m = mbase + r0 + i;
        int t = m >> 8, b = m & 255;
#pragma unroll
        for (int j = 0; j < 8; ++j) {
            int n   = nbase + c0 + j;
            int d   = n >> 12;
            int r   = n & 4095;
            int gi  = r >> 10;
            int col = r & 1023;
            size_t off = ((size_t)(d * SEQ + t) * BATCH + b) * G4 + (size_t)col * 4 + gi;
            g_XW[off] = __float2bfloat16(acc[i][j]);
        }
    }
}

// ---------------------------------------------------------------------------
// Kernel 2: one recurrent step for both directions (blockIdx.z = dir).
// GEMM: M=256 (batch), N=4096 gate-interleaved (n = col*4+gi), K=1024 (h-part).
// Fused epilogue: pre = acc + bias + XW[t]; gates; c,h update (h ping-pong).
// ---------------------------------------------------------------------------
__global__ __launch_bounds__(256) void step_kernel(int s,
    const float* __restrict__ W0, const float* __restrict__ W1,
    const float* __restrict__ W2, const float* __restrict__ W3,
    const float* __restrict__ W4, const float* __restrict__ W5,
    const float* __restrict__ W6, const float* __restrict__ W7,
    const float* __restrict__ B0, const float* __restrict__ B1,
    const float* __restrict__ B2, const float* __restrict__ B3,
    const float* __restrict__ B4, const float* __restrict__ B5,
    const float* __restrict__ B6, const float* __restrict__ B7)
{
    __shared__ __align__(16) float As[2][8][128];
    __shared__ __align__(16) float Bs[2][8][128];

    const float* Ws[8] = {W0,W1,W2,W3,W4,W5,W6,W7};
    const float* Bi[8] = {B0,B1,B2,B3,B4,B5,B6,B7};

    const int tid   = threadIdx.x;
    const int d     = blockIdx.z;
    const int nbase = blockIdx.x * 128;   // over 4096 (gate-interleaved)
    const int mbase = blockIdx.y * 128;   // over 256

    const int rb = s & 1;                 // read h buffer
    const int wb = rb ^ 1;                // write h buffer

    const int a_m = tid >> 1, a_k = (tid & 1) * 4;
    const int b_n = tid >> 1, b_k = (tid & 1) * 4;
    const int ng = nbase + b_n;           // n' = col*4 + gi
    const float* bptr = Ws[d * 4 + (ng & 3)] + (size_t)(ng >> 2) * WROW + EMB; // h part
    const float* aptr = g_h + (size_t)rb * HB2 + (size_t)d * HB
                            + (size_t)(mbase + a_m) * HID;

    float acc[8][8];
#pragma unroll
    for (int i = 0; i < 8; ++i)
#pragma unroll
        for (int j = 0; j < 8; ++j) acc[i][j] = 0.f;

    const int r0 = (tid >> 4) * 8;
    const int c0 = (tid & 15) * 8;

    gemm_core(aptr, bptr, acc, As, Bs, a_m, a_k, b_n, b_k, r0, c0, HID / 8);

    // Fused LSTM cell epilogue: this thread owns all 4 gates of 2 cols x 8 rows.
    const int t       = d ? (SEQ - 1 - s) : s;
    const int colbase = (nbase + c0) >> 2;
#pragma unroll
    for (int jj = 0; jj < 2; ++jj) {
        int col = colbase + jj;
        float bi_ = Bi[d*4+0][col];
        float bf_ = Bi[d*4+1][col];
        float bo_ = Bi[d*4+2][col];
        float bg_ = Bi[d*4+3][col];
#pragma unroll
        for (int i = 0; i < 8; ++i) {
            int b = mbase + r0 + i;
            size_t xwbase = ((size_t)(d * SEQ + t) * BATCH + b) * G4 + (size_t)col * 4;
            const __nv_bfloat162* xp = reinterpret_cast<const __nv_bfloat162*>(g_XW + xwbase);
            __nv_bfloat162 x01 = xp[0];
            __nv_bfloat162 x23 = xp[1];
            float pi = acc[i][jj*4+0] + bi_ + __low2float(x01);
            float pf = acc[i][jj*4+1] + bf_ + __high2float(x01);
            float po = acc[i][jj*4+2] + bo_ + __low2float(x23);
            float pg = acc[i][jj*4+3] + bg_ + __high2float(x23);
            float ig = 1.f / (1.f + expf(-pi));
            float fg = 1.f / (1.f + expf(-pf));
            float og = 1.f / (1.f + expf(-po));
            float gv = tanhf(pg);
            size_t hoff = (size_t)d * HB + (size_t)b * HID + col;
            float c = fg * g_c[hoff] + ig * gv;
            g_c[hoff] = c;
            g_h[(size_t)wb * HB2 + hoff] = og * tanhf(c);
        }
    }
}

// ---------------------------------------------------------------------------
// Kernel 3: hsum = h_dir0 + h_dir1 (final h lives in buffer 0 since SEQ even)
// ---------------------------------------------------------------------------
__global__ void hsum_kernel()
{
    int idx = blockIdx.x * blockDim.x + threadIdx.x;
    if (idx < HB) g_hsum[idx] = g_h[idx] + g_h[HB + idx];
}

// ---------------------------------------------------------------------------
// Kernel 4: Out[b][n] = hsum[b] . W_out[n] + b_out[n]; M=256, N=32000, K=1024
// ---------------------------------------------------------------------------
__global__ __launch_bounds__(256) void out_kernel(
    const float* __restrict__ Wout, const float* __restrict__ bout,
    float* __restrict__ out)
{
    __shared__ __align__(16) float As[2][8][128];
    __shared__ __align__(16) float Bs[2][8][128];

    const int tid   = threadIdx.x;
    const int nbase = blockIdx.x * 128;   // over 32000
    const int mbase = blockIdx.y * 128;   // over 256

    const int a_m = tid >> 1, a_k = (tid & 1) * 4;
    const int b_n = tid >> 1, b_k = (tid & 1) * 4;
    const float* aptr = g_hsum + (size_t)(mbase + a_m) * HID;
    const float* bptr = Wout + (size_t)(nbase + b_n) * HID;

    float acc[8][8];
#pragma unroll
    for (int i = 0; i < 8; ++i)
#pragma unroll
        for (int j = 0; j < 8; ++j) acc[i][j] = 0.f;

    const int r0 = (tid >> 4) * 8;
    const int c0 = (tid & 15) * 8;

    gemm_core(aptr, bptr, acc, As, Bs, a_m, a_k, b_n, b_k, r0, c0, HID / 8);

#pragma unroll
    for (int i = 0; i < 8; ++i) {
        int m = mbase + r0 + i;
#pragma unroll
        for (int j = 0; j < 8; ++j) {
            int n = nbase + c0 + j;
            out[(size_t)m * NCLS + n] = acc[i][j] + bout[n];
        }
    }
}

// ---------------------------------------------------------------------------
extern "C" void kernel_launch(void* const* d_in, const int* in_sizes, int n_in,
                              void* d_out, int out_size)
{
    (void)in_sizes; (void)n_in; (void)out_size;
    const int*   X = (const int*)d_in[0];
    const float* C = (const float*)d_in[1];
    const float* W[8];
    const float* B[8];
    for (int i = 0; i < 8; ++i) W[i] = (const float*)d_in[2 + i];
    for (int i = 0; i < 8; ++i) B[i] = (const float*)d_in[10 + i];
    const float* Wout = (const float*)d_in[18];
    const float* bout = (const float*)d_in[19];
    float* out = (float*)d_out;

    init_kernel<<<(2 * HB2 + 255) / 256, 256>>>();

    // Input projections for all timesteps, both directions: one big GEMM.
    xproj_kernel<<<dim3(64, 512), 256>>>(X, C,
        W[0], W[1], W[2], W[3], W[4], W[5], W[6], W[7]);

    // 256 recurrent steps, both directions per launch, fused LSTM cell.
    for (int s = 0; s < SEQ; ++s) {
        step_kernel<<<dim3(32, 2, 2), 256>>>(s,
            W[0], W[1], W[2], W[3], W[4], W[5], W[6], W[7],
            B[0], B[1], B[2], B[3], B[4], B[5], B[6], B[7]);
    }

    hsum_kernel<<<(HB + 255) / 256, 256>>>();
    out_kernel<<<dim3(NCLS / 128, BATCH / 128), 256>>>(Wout, bout, out);
}

// round 3
// speedup vs baseline: 4.4440x; 4.4440x over previous
#include <cuda_runtime.h>
#include <cuda_bf16.h>
#include <math.h>
#include <stdint.h>

#define BATCH 256
#define SEQ   256
#define EMB   1024
#define HID   1024
#define NCLS  32000
#define G4    4096          // 4 gates * HID
#define WROW  2048          // EMB + HID
#define HB    (BATCH*HID)   // 262144
#define HB2   (2*BATCH*HID) // 524288 (2 dirs)
#define SST   40            // smem bf16 row stride (conflict-free, 80B, 16B-aligned)
#define KS    32            // K tile depth

// Scratch (device globals: allocation-free rule)
static __device__ __nv_bfloat16 g_XW[(size_t)2 * SEQ * BATCH * G4]; // [d][t][b][col*4+gi]
static __device__ __nv_bfloat16 g_Cb[(size_t)NCLS * EMB];           // bf16 embedding table
static __device__ __nv_bfloat16 g_Whb[(size_t)2 * G4 * HID];        // [d][col*4+gi][k] h-part
static __device__ __nv_bfloat16 g_Wxb[(size_t)2 * G4 * EMB];        // [d*4096 + col*4+gi][k] x-part
static __device__ __nv_bfloat16 g_hb[2 * HB2];                      // [pingpong][dir][b][col]
static __device__ float g_c[HB2];                                   // [dir][b][col]
static __device__ float g_hsum[HB];

// ---------------------------------------------------------------------------
__global__ void init_kernel()
{
    int i = blockIdx.x * blockDim.x + threadIdx.x;
    if (i < HB2) g_c[i] = 0.f;
    if (i < HB2) reinterpret_cast<uint32_t*>(g_hb)[i] = 0u;  // 2*HB2 bf16 = HB2 u32
}

// ---------------------------------------------------------------------------
// Weight conversions to bf16 (run every launch; cheap, deterministic).
// ---------------------------------------------------------------------------
__global__ __launch_bounds__(256) void convw_kernel(
    const float* __restrict__ W0, const float* __restrict__ W1,
    const float* __restrict__ W2, const float* __restrict__ W3,
    const float* __restrict__ W4, const float* __restrict__ W5,
    const float* __restrict__ W6, const float* __restrict__ W7)
{
    const float* Ws[8] = {W0,W1,W2,W3,W4,W5,W6,W7};
    int r = blockIdx.x;             // 0..16383
    int k = threadIdx.x * 4;
    const float* src;
    __nv_bfloat16* dst;
    if (r < 8192) {                 // Whb: h-part
        int d = r >> 12, np = r & 4095, gi = np & 3, col = np >> 2;
        src = Ws[d*4 + gi] + (size_t)col * WROW + EMB + k;
        dst = g_Whb + (size_t)r * HID + k;
    } else {                        // Wxb: x-part
        int rr = r - 8192;
        int d = rr >> 12, np = rr & 4095, gi = np & 3, col = np >> 2;
        src = Ws[d*4 + gi] + (size_t)col * WROW + k;
        dst = g_Wxb + (size_t)rr * EMB + k;
    }
    float4 v = *(const float4*)src;
    __nv_bfloat162 lo; lo.x = __float2bfloat16(v.x); lo.y = __float2bfloat16(v.y);
    __nv_bfloat162 hi; hi.x = __float2bfloat16(v.z); hi.y = __float2bfloat16(v.w);
    *reinterpret_cast<__nv_bfloat162*>(dst)     = lo;
    *reinterpret_cast<__nv_bfloat162*>(dst + 2) = hi;
}

__global__ __launch_bounds__(256) void convc_kernel(const float* __restrict__ C)
{
    size_t row = blockIdx.x;
    int k = threadIdx.x * 4;
    float4 v = *(const float4*)(C + row * EMB + k);
    __nv_bfloat16* dst = g_Cb + row * EMB + k;
    __nv_bfloat162 lo; lo.x = __float2bfloat16(v.x); lo.y = __float2bfloat16(v.y);
    __nv_bfloat162 hi; hi.x = __float2bfloat16(v.z); hi.y = __float2bfloat16(v.w);
    *reinterpret_cast<__nv_bfloat162*>(dst)     = lo;
    *reinterpret_cast<__nv_bfloat162*>(dst + 2) = hi;
}

// ---------------------------------------------------------------------------
// bf16 HMMA: mma.sync.m16n8k16, fp32 accumulate.
// ---------------------------------------------------------------------------
__device__ __forceinline__ void mma_bf16(float* d, const uint32_t* a, const uint32_t* b)
{
    asm volatile(
        "mma.sync.aligned.m16n8k16.row.col.f32.bf16.bf16.f32 "
        "{%0,%1,%2,%3}, {%4,%5,%6,%7}, {%8,%9}, {%0,%1,%2,%3};\n"
        : "+f"(d[0]), "+f"(d[1]), "+f"(d[2]), "+f"(d[3])
        : "r"(a[0]), "r"(a[1]), "r"(a[2]), "r"(a[3]), "r"(b[0]), "r"(b[1]));
}

// ---------------------------------------------------------------------------
// Kernel: xproj — XW = gathered C[X] @ Wx^T (bf16 HMMA).
// M = 65536 (m = t*256+b), N = 8192 (n = d*4096 + col*4+gi), K = 1024.
// 128x128 tile, 8 warps (2m x 4n), warp tile 64x32, double-buffered smem.
// ---------------------------------------------------------------------------
__global__ __launch_bounds__(256) void xproj_mma(const int* __restrict__ X)
{
    __shared__ __align__(16) __nv_bfloat16 As[2][128*SST];
    __shared__ __align__(16) __nv_bfloat16 Bs[2][128*SST];
    __shared__ int toks[128];

    const int tid   = threadIdx.x;
    const int nbase = blockIdx.x * 128;
    const int mbase = blockIdx.y * 128;

    if (tid < 128) {
        int m = mbase + tid;
        toks[tid] = X[(m & 255) * SEQ + (m >> 8)];   // X[b][t], m = t*256+b
    }
    __syncthreads();

    const int rowA0 = tid >> 2, kc = (tid & 3) * 8;
    const __nv_bfloat16* ag0 = g_Cb + (size_t)toks[rowA0]      * EMB + kc;
    const __nv_bfloat16* ag1 = g_Cb + (size_t)toks[rowA0 + 64] * EMB + kc;
    const __nv_bfloat16* bg0 = g_Wxb + (size_t)(nbase + rowA0)      * EMB + kc;
    const __nv_bfloat16* bg1 = g_Wxb + (size_t)(nbase + rowA0 + 64) * EMB + kc;

    float acc[16][4];
#pragma unroll
    for (int i = 0; i < 16; ++i)
#pragma unroll
        for (int j = 0; j < 4; ++j) acc[i][j] = 0.f;

    const int lane = tid & 31, warp = tid >> 5;
    const int g = lane >> 2, q = lane & 3;
    const int m0 = (warp >> 2) * 64, n0 = (warp & 3) * 32;
    {
        const int sa0 = (tid >> 2) * SST + (tid & 3) * 8;
        const int sa1 = ((tid >> 2) + 64) * SST + (tid & 3) * 8;

        uint4 va0 = *(const uint4*)ag0;  ag0 += KS;
        uint4 va1 = *(const uint4*)ag1;  ag1 += KS;
        uint4 vb0 = *(const uint4*)bg0;  bg0 += KS;
        uint4 vb1 = *(const uint4*)bg1;  bg1 += KS;
        *(uint4*)&As[0][sa0] = va0;  *(uint4*)&As[0][sa1] = va1;
        *(uint4*)&Bs[0][sa0] = vb0;  *(uint4*)&Bs[0][sa1] = vb1;
        __syncthreads();

        const int nit = EMB / KS;
        for (int it = 0; it < nit; ++it) {
            const int cur = it & 1;
            if (it + 1 < nit) {
                va0 = *(const uint4*)ag0;  ag0 += KS;
                va1 = *(const uint4*)ag1;  ag1 += KS;
                vb0 = *(const uint4*)bg0;  bg0 += KS;
                vb1 = *(const uint4*)bg1;  bg1 += KS;
            }
#pragma unroll
            for (int ks = 0; ks < KS; ks += 16) {
                uint32_t af[4][4];
#pragma unroll
                for (int mi = 0; mi < 4; ++mi) {
                    const __nv_bfloat16* p = &As[cur][(m0 + mi*16 + g)*SST + ks + q*2];
                    af[mi][0] = *(const uint32_t*)p;
                    af[mi][1] = *(const uint32_t*)(p + 8*SST);
                    af[mi][2] = *(const uint32_t*)(p + 8);
                    af[mi][3] = *(const uint32_t*)(p + 8*SST + 8);
                }
                uint32_t bfr[4][2];
#pragma unroll
                for (int ni = 0; ni < 4; ++ni) {
                    const __nv_bfloat16* p = &Bs[cur][(n0 + ni*8 + g)*SST + ks + q*2];
                    bfr[ni][0] = *(const uint32_t*)p;
                    bfr[ni][1] = *(const uint32_t*)(p + 8);
                }
#pragma unroll
                for (int mi = 0; mi < 4; ++mi)
#pragma unroll
                    for (int ni = 0; ni < 4; ++ni)
                        mma_bf16(acc[mi*4 + ni], af[mi], bfr[ni]);
            }
            if (it + 1 < nit) {
                const int nxt = cur ^ 1;
                *(uint4*)&As[nxt][sa0] = va0;  *(uint4*)&As[nxt][sa1] = va1;
                *(uint4*)&Bs[nxt][sa0] = vb0;  *(uint4*)&Bs[nxt][sa1] = vb1;
                __syncthreads();
            }
        }
    }

    // Epilogue: scatter fragments to g_XW (bf16).
#pragma unroll
    for (int mi = 0; mi < 4; ++mi) {
#pragma unroll
        for (int half = 0; half < 2; ++half) {
            int r = m0 + mi*16 + g + half*8;
            int m = mbase + r;
            int t = m >> 8, b = m & 255;
#pragma unroll
            for (int ni = 0; ni < 4; ++ni) {
                int n = nbase + n0 + ni*8 + q*2;
                int d = n >> 12, rr = n & 4095;
                size_t off = ((size_t)(d * SEQ + t) * BATCH + b) * G4 + rr;
                __nv_bfloat162 v;
                v.x = __float2bfloat16(acc[mi*4 + ni][half*2 + 0]);
                v.y = __float2bfloat16(acc[mi*4 + ni][half*2 + 1]);
                *reinterpret_cast<__nv_bfloat162*>(g_XW + off) = v;
            }
        }
    }
}

// ---------------------------------------------------------------------------
// Kernel: one recurrent step (bf16 HMMA) + fused LSTM cell via smem staging.
// M=256 (batch), N=4096 gate-interleaved per dir, K=1024.
// ---------------------------------------------------------------------------
__global__ __launch_bounds__(256) void step_mma(int s,
    const float* __restrict__ B0, const float* __restrict__ B1,
    const float* __restrict__ B2, const float* __restrict__ B3,
    const float* __restrict__ B4, const float* __restrict__ B5,
    const float* __restrict__ B6, const float* __restrict__ B7)
{
    __shared__ __align__(16) unsigned char smraw[40960]; // A/B double-buf OR pre[64][132]
    __nv_bfloat16 (*As)[128*SST] = reinterpret_cast<__nv_bfloat16 (*)[128*SST]>(smraw);
    __nv_bfloat16 (*Bs)[128*SST] = reinterpret_cast<__nv_bfloat16 (*)[128*SST]>(smraw + 2*128*SST*sizeof(__nv_bfloat16));
    float (*pre)[132] = reinterpret_cast<float (*)[132]>(smraw);

    const float* Bi[8] = {B0,B1,B2,B3,B4,B5,B6,B7};

    const int tid   = threadIdx.x;
    const int d     = blockIdx.z;
    const int nbase = blockIdx.x * 128;   // over 4096 (n' = col*4+gi)
    const int mbase = blockIdx.y * 128;   // over 256
    const int rb    = s & 1, wb = rb ^ 1;

    const int rowA0 = tid >> 2, kc = (tid & 3) * 8;
    const __nv_bfloat16* ag0 = g_hb + (size_t)rb*HB2 + (size_t)d*HB
                                    + (size_t)(mbase + rowA0) * HID + kc;
    const __nv_bfloat16* ag1 = ag0 + (size_t)64 * HID;
    const __nv_bfloat16* bg0 = g_Whb + ((size_t)d*G4 + nbase + rowA0) * HID + kc;
    const __nv_bfloat16* bg1 = bg0 + (size_t)64 * HID;

    float acc[16][4];
#pragma unroll
    for (int i = 0; i < 16; ++i)
#pragma unroll
        for (int j = 0; j < 4; ++j) acc[i][j] = 0.f;

    const int lane = tid & 31, warp = tid >> 5;
    const int g = lane >> 2, q = lane & 3;
    const int m0 = (warp >> 2) * 64, n0 = (warp & 3) * 32;
    {
        const int sa0 = (tid >> 2) * SST + (tid & 3) * 8;
        const int sa1 = ((tid >> 2) + 64) * SST + (tid & 3) * 8;

        uint4 va0 = *(const uint4*)ag0;  ag0 += KS;
        uint4 va1 = *(const uint4*)ag1;  ag1 += KS;
        uint4 vb0 = *(const uint4*)bg0;  bg0 += KS;
        uint4 vb1 = *(const uint4*)bg1;  bg1 += KS;
        *(uint4*)&As[0][sa0] = va0;  *(uint4*)&As[0][sa1] = va1;
        *(uint4*)&Bs[0][sa0] = vb0;  *(uint4*)&Bs[0][sa1] = vb1;
        __syncthreads();

        const int nit = HID / KS;
        for (int it = 0; it < nit; ++it) {
            const int cur = it & 1;
            if (it + 1 < nit) {
                va0 = *(const uint4*)ag0;  ag0 += KS;
                va1 = *(const uint4*)ag1;  ag1 += KS;
                vb0 = *(const uint4*)bg0;  bg0 += KS;
                vb1 = *(const uint4*)bg1;  bg1 += KS;
            }
#pragma unroll
            for (int ks = 0; ks < KS; ks += 16) {
                uint32_t af[4][4];
#pragma unroll
                for (int mi = 0; mi < 4; ++mi) {
                    const __nv_bfloat16* p = &As[cur][(m0 + mi*16 + g)*SST + ks + q*2];
                    af[mi][0] = *(const uint32_t*)p;
                    af[mi][1] = *(const uint32_t*)(p + 8*SST);
                    af[mi][2] = *(const uint32_t*)(p + 8);
                    af[mi][3] = *(const uint32_t*)(p + 8*SST + 8);
                }
                uint32_t bfr[4][2];
#pragma unroll
                for (int ni = 0; ni < 4; ++ni) {
                    const __nv_bfloat16* p = &Bs[cur][(n0 + ni*8 + g)*SST + ks + q*2];
                    bfr[ni][0] = *(const uint32_t*)p;
                    bfr[ni][1] = *(const uint32_t*)(p + 8);
                }
#pragma unroll
                for (int mi = 0; mi < 4; ++mi)
#pragma unroll
                    for (int ni = 0; ni < 4; ++ni)
                        mma_bf16(acc[mi*4 + ni], af[mi], bfr[ni]);
            }
            if (it + 1 < nit) {
                const int nxt = cur ^ 1;
                *(uint4*)&As[nxt][sa0] = va0;  *(uint4*)&As[nxt][sa1] = va1;
                *(uint4*)&Bs[nxt][sa0] = vb0;  *(uint4*)&Bs[nxt][sa1] = vb1;
                __syncthreads();
            }
        }
    }
    __syncthreads();   // done with A/B smem; reuse as preact staging

    // Fused LSTM cell epilogue, two 64-row halves through smem.
    const int t = d ? (SEQ - 1 - s) : s;
    const float* bI = Bi[d*4 + 0];
    const float* bF = Bi[d*4 + 1];
    const float* bO = Bi[d*4 + 2];
    const float* bG = Bi[d*4 + 3];

#pragma unroll
    for (int hh = 0; hh < 2; ++hh) {
        if ((warp >> 2) == hh) {
#pragma unroll
            for (int mi = 0; mi < 4; ++mi)
#pragma unroll
                for (int half = 0; half < 2; ++half) {
                    int rl = mi*16 + g + half*8;   // local row 0..63
#pragma unroll
                    for (int ni = 0; ni < 4; ++ni) {
                        int c = n0 + ni*8 + q*2;
                        float2 v;
                        v.x = acc[mi*4 + ni][half*2 + 0];
                        v.y = acc[mi*4 + ni][half*2 + 1];
                        *reinterpret_cast<float2*>(&pre[rl][c]) = v;
                    }
                }
        }
        __syncthreads();

        const int row = tid >> 5;    // 0..7
        const int cl  = tid & 31;    // cell within tile
#pragma unroll
        for (int e = 0; e < 8; ++e) {
            int r = row + e * 8;                 // 0..63
            int b = mbase + hh*64 + r;
            int col = (nbase >> 2) + cl;
            float4 p = *reinterpret_cast<const float4*>(&pre[r][cl*4]);

            size_t xwoff = ((size_t)(d*SEQ + t) * BATCH + b) * G4 + (size_t)(nbase + cl*4);
            uint2 xw = *reinterpret_cast<const uint2*>(g_XW + xwoff);
            __nv_bfloat162 x01 = *reinterpret_cast<__nv_bfloat162*>(&xw.x);
            __nv_bfloat162 x23 = *reinterpret_cast<__nv_bfloat162*>(&xw.y);

            float pi = p.x + bI[col] + __low2float(x01);
            float pf = p.y + bF[col] + __high2float(x01);
            float po = p.z + bO[col] + __low2float(x23);
            float pg = p.w + bG[col] + __high2float(x23);

            float ig = 1.f / (1.f + expf(-pi));
            float fg = 1.f / (1.f + expf(-pf));
            float og = 1.f / (1.f + expf(-po));
            float gv = tanhf(pg);

            size_t hoff = (size_t)d*HB + (size_t)b*HID + col;
            float cc = fg * g_c[hoff] + ig * gv;
            g_c[hoff] = cc;
            g_hb[(size_t)wb*HB2 + hoff] = __float2bfloat16(og * tanhf(cc));
        }
        __syncthreads();
    }
}

// ---------------------------------------------------------------------------
// hsum = h_dir0 + h_dir1 (final h in buffer 0, fp32 for the output GEMM)
// ---------------------------------------------------------------------------
__global__ void hsum_kernel()
{
    int i = blockIdx.x * blockDim.x + threadIdx.x;
    if (i < HB)
        g_hsum[i] = __bfloat162float(g_hb[i]) + __bfloat162float(g_hb[HB + i]);
}

// ---------------------------------------------------------------------------
// Output GEMM kept in fp32 FFMA for precision: M=256, N=32000, K=1024.
// ---------------------------------------------------------------------------
__device__ __forceinline__ void gemm_core_f32(
    const float* __restrict__ aptr, const float* __restrict__ bptr,
    float (&acc)[8][8],
    float (*As)[8][128], float (*Bs)[8][128],
    int a_m, int a_k, int b_n, int b_k, int r0, int c0, int nit)
{
    float4 pa = *(const float4*)(aptr + a_k);
    float4 pb = *(const float4*)(bptr + b_k);
    As[0][a_k+0][a_m]=pa.x; As[0][a_k+1][a_m]=pa.y; As[0][a_k+2][a_m]=pa.z; As[0][a_k+3][a_m]=pa.w;
    Bs[0][b_k+0][b_n]=pb.x; Bs[0][b_k+1][b_n]=pb.y; Bs[0][b_k+2][b_n]=pb.z; Bs[0][b_k+3][b_n]=pb.w;
    __syncthreads();

    for (int it = 0; it < nit; ++it) {
        int cur = it & 1;
        if (it + 1 < nit) {
            int k0 = (it + 1) * 8;
            pa = *(const float4*)(aptr + k0 + a_k);
            pb = *(const float4*)(bptr + k0 + b_k);
        }
#pragma unroll
        for (int kk = 0; kk < 8; ++kk) {
            float4 x0 = *(const float4*)&As[cur][kk][r0];
            float4 x1 = *(const float4*)&As[cur][kk][r0+4];
            float4 y0 = *(const float4*)&Bs[cur][kk][c0];
            float4 y1 = *(const float4*)&Bs[cur][kk][c0+4];
            float a[8] = {x0.x,x0.y,x0.z,x0.w,x1.x,x1.y,x1.z,x1.w};
            float b[8] = {y0.x,y0.y,y0.z,y0.w,y1.x,y1.y,y1.z,y1.w};
#pragma unroll
            for (int i = 0; i < 8; ++i)
#pragma unroll
                for (int j = 0; j < 8; ++j)
                    acc[i][j] = fmaf(a[i], b[j], acc[i][j]);
        }
        if (it + 1 < nit) {
            int nxt = cur ^ 1;
            As[nxt][a_k+0][a_m]=pa.x; As[nxt][a_k+1][a_m]=pa.y; As[nxt][a_k+2][a_m]=pa.z; As[nxt][a_k+3][a_m]=pa.w;
            Bs[nxt][b_k+0][b_n]=pb.x; Bs[nxt][b_k+1][b_n]=pb.y; Bs[nxt][b_k+2][b_n]=pb.z; Bs[nxt][b_k+3][b_n]=pb.w;
            __syncthreads();
        }
    }
}

__global__ __launch_bounds__(256) void out_kernel(
    const float* __restrict__ Wout, const float* __restrict__ bout,
    float* __restrict__ out)
{
    __shared__ __align__(16) float As[2][8][128];
    __shared__ __align__(16) float Bs[2][8][128];

    const int tid   = threadIdx.x;
    const int nbase = blockIdx.x * 128;
    const int mbase = blockIdx.y * 128;

    const int a_m = tid >> 1, a_k = (tid & 1) * 4;
    const int b_n = tid >> 1, b_k = (tid & 1) * 4;
    const float* aptr = g_hsum + (size_t)(mbase + a_m) * HID;
    const float* bptr = Wout + (size_t)(nbase + b_n) * HID;

    float acc[8][8];
#pragma unroll
    for (int i = 0; i < 8; ++i)
#pragma unroll
        for (int j = 0; j < 8; ++j) acc[i][j] = 0.f;

    const int r0 = (tid >> 4) * 8;
    const int c0 = (tid & 15) * 8;

    gemm_core_f32(aptr, bptr, acc, As, Bs, a_m, a_k, b_n, b_k, r0, c0, HID / 8);

#pragma unroll
    for (int i = 0; i < 8; ++i) {
        int m = mbase + r0 + i;
#pragma unroll
        for (int j = 0; j < 8; ++j) {
            int n = nbase + c0 + j;
            out[(size_t)m * NCLS + n] = acc[i][j] + bout[n];
        }
    }
}

// ---------------------------------------------------------------------------
extern "C" void kernel_launch(void* const* d_in, const int* in_sizes, int n_in,
                              void* d_out, int out_size)
{
    (void)in_sizes; (void)n_in; (void)out_size;
    const int*   X = (const int*)d_in[0];
    const float* C = (const float*)d_in[1];
    const float* W[8];
    const float* B[8];
    for (int i = 0; i < 8; ++i) W[i] = (const float*)d_in[2 + i];
    for (int i = 0; i < 8; ++i) B[i] = (const float*)d_in[10 + i];
    const float* Wout = (const float*)d_in[18];
    const float* bout = (const float*)d_in[19];
    float* out = (float*)d_out;

    init_kernel<<<(HB2 + 255) / 256, 256>>>();
    convw_kernel<<<16384, 256>>>(W[0],W[1],W[2],W[3],W[4],W[5],W[6],W[7]);
    convc_kernel<<<NCLS, 256>>>(C);

    // Input projections for all timesteps, both directions (tensor cores).
    xproj_mma<<<dim3(64, 512), 256>>>(X);

    // 256 recurrent steps (tensor cores, fused LSTM cell).
    for (int s = 0; s < SEQ; ++s) {
        step_mma<<<dim3(32, 2, 2), 256>>>(s,
            B[0], B[1], B[2], B[3], B[4], B[5], B[6], B[7]);
    }

    hsum_kernel<<<(HB + 255) / 256, 256>>>();
    out_kernel<<<dim3(NCLS / 128, BATCH / 128), 256>>>(Wout, bout, out);
}